// round 2
// baseline (speedup 1.0000x reference)
#include <cuda_runtime.h>
#include <math.h>

#define BB 64
#define SS 128
#define HH 1024
#define EE 1024
#define EMBD 512
#define VV 32000
#define TT 50
#define G4 4096
#define NPRED (64*50*32000)

// ---------------- device scratch (static, no runtime alloc) ----------------
__device__ __align__(16) float g_h[BB*HH];
__device__ __align__(16) float g_c[BB*HH];
__device__ __align__(16) float g_prev[BB*EMBD];
__device__ __align__(16) float g_ct[BB*EE];
__device__ __align__(16) float g_gpart[8*BB*G4];   // split-K partials for gates
__device__ __align__(16) float g_qpart[8*BB*EE];   // split-K partials for q
__device__ __align__(16) float g_dpart[8*BB*EMBD]; // split-K partials for dec
__device__ unsigned long long g_amax[BB];

// ---------------- helpers ----------------
__device__ __forceinline__ float sigmoidf_(float x){ return 1.f/(1.f+expf(-x)); }

// pack (value, index) so that atomicMax == argmax with first-index tie-break
__device__ __forceinline__ unsigned long long packmax(float v, int n){
  unsigned int b = __float_as_uint(v);
  b = (b & 0x80000000u) ? ~b : (b | 0x80000000u);
  return ((unsigned long long)b << 32) | (unsigned int)(0x7FFFFFFF - n);
}

// Load a 64(rows) x 16(k) tile from row-major src[row*ld + koff+k] into sm[k][row], stride 68
__device__ __forceinline__ void ldT(float* sm, const float* __restrict__ src, int ld, int koff, int tid){
  int r = tid >> 2, q = tid & 3;
  const float4 v = *reinterpret_cast<const float4*>(src + (size_t)r*ld + koff + 4*q);
  sm[(4*q+0)*68 + r] = v.x;
  sm[(4*q+1)*68 + r] = v.y;
  sm[(4*q+2)*68 + r] = v.z;
  sm[(4*q+3)*68 + r] = v.w;
}

// Load a 16(k) x 64(n) tile from k-major src[(k0+k)*ldn + n] (src pre-offset by n0)
__device__ __forceinline__ void ldD(float* sm, const float* __restrict__ src, int ldn, int k0, int tid){
  int k = tid >> 4, n4 = tid & 15;
  const float4 v = *reinterpret_cast<const float4*>(src + (size_t)(k0+k)*ldn + 4*n4);
  *reinterpret_cast<float4*>(&sm[k*68 + 4*n4]) = v;
}

__device__ __forceinline__ void mmacc(const float* As, const float* Bs, int tx, int ty, float acc[4][4]){
#pragma unroll
  for (int kk = 0; kk < 16; ++kk){
    float4 a = *reinterpret_cast<const float4*>(&As[kk*68 + 4*ty]);
    float4 b = *reinterpret_cast<const float4*>(&Bs[kk*68 + 4*tx]);
    float av[4] = {a.x,a.y,a.z,a.w};
    float bv[4] = {b.x,b.y,b.z,b.w};
#pragma unroll
    for (int i = 0; i < 4; ++i)
#pragma unroll
      for (int j = 0; j < 4; ++j)
        acc[i][j] = fmaf(av[i], bv[j], acc[i][j]);
  }
}

// ---------------- init ----------------
__global__ void k_init(const float* __restrict__ ds){
  int idx = blockIdx.x*blockDim.x + threadIdx.x;   // 65536 threads
  g_h[idx] = ds[idx];           // dec_initial_state[0,0,b,h]
  g_c[idx] = ds[65536 + idx];   // dec_initial_state[1,0,b,h]
  if (idx < BB*EMBD) g_prev[idx] = 0.f;
}

// ---------------- gates: [prev|h] @ [W_ih|W_hh]^T, split-K into 8 parts ----------------
__global__ void k_gates(const float* __restrict__ Wih, const float* __restrict__ Whh){
  __shared__ __align__(16) float As[16*68];
  __shared__ __align__(16) float Bs[16*68];
  int tid = threadIdx.x, tx = tid & 15, ty = tid >> 4;
  int n0 = blockIdx.x*64, part = blockIdx.y;
  float acc[4][4] = {};
  for (int kt = 0; kt < 12; ++kt){
    int k = (part*12 + kt)*16;   // k in [0,1536)
    if (k < 512){ ldT(As, g_prev, 512, k, tid);       ldT(Bs, Wih + (size_t)n0*512, 512, k, tid); }
    else        { ldT(As, g_h, 1024, k-512, tid);     ldT(Bs, Whh + (size_t)n0*1024, 1024, k-512, tid); }
    __syncthreads();
    mmacc(As, Bs, tx, ty, acc);
    __syncthreads();
  }
  float* out = g_gpart + (size_t)part*BB*G4;
#pragma unroll
  for (int i = 0; i < 4; ++i)
#pragma unroll
    for (int j = 0; j < 4; ++j)
      out[(size_t)(ty*4+i)*G4 + n0 + tx*4 + j] = acc[i][j];
}

// ---------------- LSTM elementwise (sums split-K parts + bias) ----------------
__global__ void k_lstm(const float* __restrict__ bl){
  int idx = blockIdx.x*blockDim.x + threadIdx.x;   // 65536
  int m = idx >> 10, j = idx & 1023;
  float gi = bl[j], gf = bl[1024+j], gg = bl[2048+j], go = bl[3072+j];
#pragma unroll
  for (int p = 0; p < 8; ++p){
    const float* gp = g_gpart + (size_t)p*BB*G4 + (size_t)m*G4 + j;
    gi += gp[0]; gf += gp[1024]; gg += gp[2048]; go += gp[3072];
  }
  float c = g_c[idx];
  float cn = sigmoidf_(gf)*c + sigmoidf_(gi)*tanhf(gg);
  g_c[idx] = cn;
  g_h[idx] = sigmoidf_(go)*tanhf(cn);
}

// ---------------- q = h @ W_attproj  (q[b,e] = sum_k h[b,k] Wap[k,e]) ----------------
__global__ void k_q(const float* __restrict__ Wap){
  __shared__ __align__(16) float As[16*68];
  __shared__ __align__(16) float Bs[16*68];
  int tid = threadIdx.x, tx = tid & 15, ty = tid >> 4;
  int n0 = blockIdx.x*64, part = blockIdx.y;
  float acc[4][4] = {};
  for (int kt = 0; kt < 8; ++kt){
    int k = (part*8 + kt)*16;   // k in [0,1024)
    ldT(As, g_h, 1024, k, tid);
    ldD(Bs, Wap + n0, EE, k, tid);
    __syncthreads();
    mmacc(As, Bs, tx, ty, acc);
    __syncthreads();
  }
  float* out = g_qpart + (size_t)part*BB*EE;
#pragma unroll
  for (int i = 0; i < 4; ++i)
#pragma unroll
    for (int j = 0; j < 4; ++j)
      out[(size_t)(ty*4+i)*EE + n0 + tx*4 + j] = acc[i][j];
}

// ---------------- fused attention: scores -> masked softmax -> context ----------------
__global__ void k_attn(const float* __restrict__ enc, const int* __restrict__ enc_len){
  __shared__ float qv[1024];
  __shared__ float sc[128];
  __shared__ float sr[256];
  int tid = threadIdx.x, b = blockIdx.x;
  for (int e = tid; e < 1024; e += 256){
    float s = 0.f;
#pragma unroll
    for (int p = 0; p < 8; ++p) s += g_qpart[(size_t)p*BB*EE + (size_t)b*EE + e];
    qv[e] = s;
  }
  __syncthreads();
  const float* eb = enc + (size_t)b*SS*EE;
  int w = tid >> 5, lane = tid & 31;
  for (int s = w; s < 128; s += 8){
    const float* er = eb + (size_t)s*EE;
    float acc = 0.f;
    for (int e = lane; e < 1024; e += 32) acc = fmaf(er[e], qv[e], acc);
#pragma unroll
    for (int o = 16; o; o >>= 1) acc += __shfl_xor_sync(0xffffffffu, acc, o);
    if (lane == 0) sc[s] = acc;
  }
  __syncthreads();
  int len = enc_len[b];
  float v = -3.0e38f;
  if (tid < 128) v = (tid < len) ? sc[tid] : -1e9f;
  sr[tid] = v; __syncthreads();
  for (int o = 128; o; o >>= 1){ if (tid < o) sr[tid] = fmaxf(sr[tid], sr[tid+o]); __syncthreads(); }
  float mx = sr[0]; __syncthreads();
  float ev = 0.f;
  if (tid < 128) ev = expf(v - mx);
  sr[tid] = ev; __syncthreads();
  for (int o = 128; o; o >>= 1){ if (tid < o) sr[tid] += sr[tid+o]; __syncthreads(); }
  float inv = 1.f / sr[0];
  __syncthreads();
  if (tid < 128) sc[tid] = ev * inv;
  __syncthreads();
  float a0=0.f, a1=0.f, a2=0.f, a3=0.f;
  for (int s = 0; s < 128; ++s){
    float al = sc[s];
    const float* er = eb + (size_t)s*EE;
    a0 = fmaf(al, er[tid      ], a0);
    a1 = fmaf(al, er[tid + 256], a1);
    a2 = fmaf(al, er[tid + 512], a2);
    a3 = fmaf(al, er[tid + 768], a3);
  }
  float* ct = g_ct + (size_t)b*EE;
  ct[tid] = a0; ct[tid+256] = a1; ct[tid+512] = a2; ct[tid+768] = a3;
}

// ---------------- dec = [h | c_t] @ W_out^T, split-K 8 ----------------
__global__ void k_dec(const float* __restrict__ Wout){
  __shared__ __align__(16) float As[16*68];
  __shared__ __align__(16) float Bs[16*68];
  int tid = threadIdx.x, tx = tid & 15, ty = tid >> 4;
  int n0 = blockIdx.x*64, part = blockIdx.y;
  float acc[4][4] = {};
  for (int kt = 0; kt < 16; ++kt){
    int k = (part*16 + kt)*16;   // k in [0,2048)
    if (k < 1024) ldT(As, g_h, 1024, k, tid);
    else          ldT(As, g_ct, 1024, k-1024, tid);
    ldT(Bs, Wout + (size_t)n0*2048, 2048, k, tid);
    __syncthreads();
    mmacc(As, Bs, tx, ty, acc);
    __syncthreads();
  }
  float* out = g_dpart + (size_t)part*BB*EMBD;
#pragma unroll
  for (int i = 0; i < 4; ++i)
#pragma unroll
    for (int j = 0; j < 4; ++j)
      out[(size_t)(ty*4+i)*EMBD + n0 + tx*4 + j] = acc[i][j];
}

__global__ void k_reset(){ g_amax[threadIdx.x] = 0ull; }

// ---------------- logits = dec @ W_vocab^T -> d_out, + block argmax ----------------
__global__ void k_vocab(const float* __restrict__ Wv, float* __restrict__ out, int t){
  __shared__ __align__(16) float As[16*68];
  __shared__ __align__(16) float Bs[16*68];
  __shared__ unsigned long long red[64];
  int tid = threadIdx.x, tx = tid & 15, ty = tid >> 4;
  int n0 = blockIdx.x*64;
  if (tid < 64) red[tid] = 0ull;
  float acc[4][4] = {};
  for (int kt = 0; kt < 32; ++kt){
    int k = kt*16;
    { // A = sum of 8 dec split-K parts
      int r = tid >> 2, q = tid & 3;
      float4 v = make_float4(0.f,0.f,0.f,0.f);
#pragma unroll
      for (int p = 0; p < 8; ++p){
        const float4 w = *reinterpret_cast<const float4*>(g_dpart + ((size_t)p*BB + r)*EMBD + k + 4*q);
        v.x += w.x; v.y += w.y; v.z += w.z; v.w += w.w;
      }
      As[(4*q+0)*68 + r] = v.x;
      As[(4*q+1)*68 + r] = v.y;
      As[(4*q+2)*68 + r] = v.z;
      As[(4*q+3)*68 + r] = v.w;
    }
    ldT(Bs, Wv + (size_t)n0*512, 512, k, tid);
    __syncthreads();
    mmacc(As, Bs, tx, ty, acc);
    __syncthreads();
  }
#pragma unroll
  for (int i = 0; i < 4; ++i){
    int m = ty*4 + i;
    float bv = acc[i][0]; int bn = n0 + tx*4;
#pragma unroll
    for (int j = 1; j < 4; ++j)
      if (acc[i][j] > bv){ bv = acc[i][j]; bn = n0 + tx*4 + j; }
    atomicMax(&red[m], packmax(bv, bn));
    float* orow = out + ((size_t)m*TT + t)*VV + n0 + tx*4;
#pragma unroll
    for (int j = 0; j < 4; ++j) orow[j] = acc[i][j];
  }
  __syncthreads();
  if (tid < 64) atomicMax(&g_amax[tid], red[tid]);
}

// ---------------- greedy symbol -> prev embedding ----------------
__global__ void k_update(const float* __restrict__ emb){
  int b = blockIdx.x;
  unsigned int low = (unsigned int)(g_amax[b] & 0xFFFFFFFFull);
  int sym = 0x7FFFFFFF - (int)low;
  g_prev[(size_t)b*EMBD + threadIdx.x] = emb[(size_t)sym*EMBD + threadIdx.x];
}

// ---------------- in-place log-softmax over V ----------------
__global__ void k_lsm(float* __restrict__ out){
  __shared__ float sr[256];
  float* p = out + (size_t)blockIdx.x * VV;
  int tid = threadIdx.x;
  float mx = -3.4e38f;
  for (int i = tid; i < VV; i += 256) mx = fmaxf(mx, p[i]);
  sr[tid] = mx; __syncthreads();
  for (int o = 128; o; o >>= 1){ if (tid < o) sr[tid] = fmaxf(sr[tid], sr[tid+o]); __syncthreads(); }
  mx = sr[0]; __syncthreads();
  float s = 0.f;
  for (int i = tid; i < VV; i += 256) s += expf(p[i] - mx);
  sr[tid] = s; __syncthreads();
  for (int o = 128; o; o >>= 1){ if (tid < o) sr[tid] += sr[tid+o]; __syncthreads(); }
  float shift = mx + logf(sr[0]);
  __syncthreads();
  for (int i = tid; i < VV; i += 256) p[i] = p[i] - shift;
}

// tl is provably always T=50 (see analysis): last-EOS update at t=T-1 gives 50,
// and non-EOS-at-final rows are overwritten with T=50.
__global__ void k_tail(float* __restrict__ out){ out[NPRED + threadIdx.x] = 50.0f; }

extern "C" void kernel_launch(void* const* d_in, const int* in_sizes, int n_in,
                              void* d_out, int out_size){
  const float* ds   = (const float*)d_in[0];
  const float* enc  = (const float*)d_in[1];
  const int*   elen = (const int*)  d_in[2];
  // d_in[3] = tgt (unused in eval mode)
  const float* Wih  = (const float*)d_in[4];
  const float* Whh  = (const float*)d_in[5];
  const float* bl   = (const float*)d_in[6];
  const float* Wap  = (const float*)d_in[7];
  const float* Wout = (const float*)d_in[8];
  const float* Wv   = (const float*)d_in[9];
  const float* emb  = (const float*)d_in[10];
  float* out = (float*)d_out;

  k_init<<<256,256>>>(ds);
  for (int t = 0; t < TT; ++t){
    k_gates<<<dim3(64,8),256>>>(Wih, Whh);
    k_lstm<<<256,256>>>(bl);
    k_q<<<dim3(16,8),256>>>(Wap);
    k_attn<<<64,256>>>(enc, elen);
    k_dec<<<dim3(8,8),256>>>(Wout);
    k_reset<<<1,64>>>();
    k_vocab<<<500,256>>>(Wv, out, t);
    k_update<<<64,512>>>(emb);
  }
  k_lsm<<<3200,256>>>(out);
  if (out_size >= NPRED + 64) k_tail<<<1,64>>>(out);
}

// round 3
// speedup vs baseline: 1.4362x; 1.4362x over previous
#include <cuda_runtime.h>
#include <math.h>

#define BB 64
#define SS 128
#define HH 1024
#define EE 1024
#define EMBD 512
#define VV 32000
#define TT 50
#define G4 4096
#define NPRED (64*50*32000)

typedef unsigned long long ull;

// ---------------- device scratch (static, no runtime alloc) ----------------
__device__ __align__(16) float g_h[BB*HH];
__device__ __align__(16) float g_c[BB*HH];
__device__ __align__(16) float g_prev[BB*EMBD];
__device__ __align__(16) float g_ct[BB*EE];
__device__ __align__(16) float g_dec[BB*EMBD];
__device__ __align__(16) float g_gpart[4*BB*G4];   // split-K partials for gates
__device__ __align__(16) float g_qpart[8*BB*EE];   // split-K partials for q
__device__ __align__(16) float g_dpart[8*BB*EMBD]; // split-K partials for dec
__device__ ull g_amax[BB];

// ---------------- helpers ----------------
__device__ __forceinline__ float sigmoidf_(float x){ return 1.f/(1.f+expf(-x)); }

// pack (value, index) so that atomicMax == argmax with first-index tie-break
__device__ __forceinline__ ull packmax(float v, int n){
  unsigned int b = __float_as_uint(v);
  b = (b & 0x80000000u) ? ~b : (b | 0x80000000u);
  return ((ull)b << 32) | (unsigned int)(0x7FFFFFFF - n);
}

// packed fp32x2 FMA (Blackwell): d = a*b + d lanewise
__device__ __forceinline__ void ffma2(ull &d, ull a, ull b){
  asm("fma.rn.f32x2 %0, %1, %2, %0;" : "+l"(d) : "l"(a), "l"(b));
}
__device__ __forceinline__ ull pk2(float x){
  ull r; asm("mov.b64 %0, {%1, %1};" : "=l"(r) : "f"(x)); return r;
}
__device__ __forceinline__ float2 unpk(ull v){
  float2 r; asm("mov.b64 {%0, %1}, %2;" : "=f"(r.x), "=f"(r.y) : "l"(v)); return r;
}

// ---------------- GEMM loaders (64 x 128 tile, BK=16, 256 threads) ----------------
// A: 64 rows x 16 k from (possibly concatenated) row-major sources -> As[k][m], stride 68
struct ALd {
  const float *s0, *s1; int ld0, ld1, cut, tid; float4 v;
  __device__ __forceinline__ void ldg(int k){
    int r = tid >> 2, q = tid & 3;
    const float* s; int ld, kk;
    if (k < cut){ s = s0; ld = ld0; kk = k; } else { s = s1; ld = ld1; kk = k - cut; }
    v = *reinterpret_cast<const float4*>(s + (size_t)r*ld + kk + 4*q);
  }
  __device__ __forceinline__ void sts(float* As) const {
    int r = tid >> 2, q = tid & 3;
    As[(4*q+0)*68+r] = v.x; As[(4*q+1)*68+r] = v.y;
    As[(4*q+2)*68+r] = v.z; As[(4*q+3)*68+r] = v.w;
  }
};
// B from row-major W[n][k] (transpose on store) -> Bs[k][n], stride 132
struct BLdT {
  const float *s0, *s1; int ld0, ld1, cut, tid; float4 v0, v1;
  __device__ __forceinline__ void ldg(int k){
    int n = tid >> 1, q = tid & 1;
    const float* s; int ld, kk;
    if (k < cut){ s = s0; ld = ld0; kk = k; } else { s = s1; ld = ld1; kk = k - cut; }
    const float* p = s + (size_t)n*ld + kk + 8*q;
    v0 = *reinterpret_cast<const float4*>(p);
    v1 = *reinterpret_cast<const float4*>(p+4);
  }
  __device__ __forceinline__ void sts(float* Bs) const {
    int n = tid >> 1, kb = (tid & 1)*8;
    Bs[(kb+0)*132+n]=v0.x; Bs[(kb+1)*132+n]=v0.y; Bs[(kb+2)*132+n]=v0.z; Bs[(kb+3)*132+n]=v0.w;
    Bs[(kb+4)*132+n]=v1.x; Bs[(kb+5)*132+n]=v1.y; Bs[(kb+6)*132+n]=v1.z; Bs[(kb+7)*132+n]=v1.w;
  }
};
// B from k-major W[k][n] (no transpose) -> Bs[k][n]
struct BLdD {
  const float* s; int ldn, tid; float4 v0, v1;
  __device__ __forceinline__ void ldg(int k){
    int kk = tid >> 4, nq = tid & 15;
    const float* p = s + (size_t)(k+kk)*ldn + 8*nq;
    v0 = *reinterpret_cast<const float4*>(p);
    v1 = *reinterpret_cast<const float4*>(p+4);
  }
  __device__ __forceinline__ void sts(float* Bs) const {
    int kk = tid >> 4, nq = tid & 15;
    *reinterpret_cast<float4*>(&Bs[kk*132 + 8*nq])   = v0;
    *reinterpret_cast<float4*>(&Bs[kk*132 + 8*nq+4]) = v1;
  }
};

// core: double-buffered, packed f32x2 accumulation. accv[i2][j] holds rows (8ty+2*i2, +1)
template<class AL, class BL>
__device__ __forceinline__ void gemm_run(AL a, BL b, int kbase, int ntiles,
                                         ull accv[4][4], int tx, int ty){
  __shared__ __align__(16) float As[2][16*68];
  __shared__ __align__(16) float Bs[2][16*132];
  a.ldg(kbase); b.ldg(kbase);
  a.sts(As[0]); b.sts(Bs[0]);
  __syncthreads();
  int cur = 0;
  for (int kt = 0; kt < ntiles; ++kt){
    bool more = (kt+1) < ntiles;
    if (more){ a.ldg(kbase + (kt+1)*16); b.ldg(kbase + (kt+1)*16); }
    const float* Ac = As[cur]; const float* Bc = Bs[cur];
#pragma unroll
    for (int kk = 0; kk < 16; ++kk){
      const longlong2* ap = reinterpret_cast<const longlong2*>(&Ac[kk*68 + 8*ty]);
      longlong2 aA = ap[0], aB = ap[1];
      float4 bf = *reinterpret_cast<const float4*>(&Bc[kk*132 + 4*tx]);
      ull av[4] = {(ull)aA.x, (ull)aA.y, (ull)aB.x, (ull)aB.y};
      ull bv[4] = {pk2(bf.x), pk2(bf.y), pk2(bf.z), pk2(bf.w)};
#pragma unroll
      for (int i2 = 0; i2 < 4; ++i2)
#pragma unroll
        for (int j = 0; j < 4; ++j)
          ffma2(accv[i2][j], av[i2], bv[j]);
    }
    if (more){ a.sts(As[cur^1]); b.sts(Bs[cur^1]); __syncthreads(); cur ^= 1; }
  }
}

// unpack accv -> c[8][4] (c[i][j] = C[8ty+i][4tx+j])
__device__ __forceinline__ void unpack_acc(const ull accv[4][4], float c[8][4]){
#pragma unroll
  for (int i2 = 0; i2 < 4; ++i2){
    float2 u0 = unpk(accv[i2][0]), u1 = unpk(accv[i2][1]);
    float2 u2 = unpk(accv[i2][2]), u3 = unpk(accv[i2][3]);
    c[2*i2  ][0]=u0.x; c[2*i2  ][1]=u1.x; c[2*i2  ][2]=u2.x; c[2*i2  ][3]=u3.x;
    c[2*i2+1][0]=u0.y; c[2*i2+1][1]=u1.y; c[2*i2+1][2]=u2.y; c[2*i2+1][3]=u3.y;
  }
}

// ---------------- init ----------------
__global__ void k_init(const float* __restrict__ ds){
  int idx = blockIdx.x*blockDim.x + threadIdx.x;   // 65536 threads
  g_h[idx] = ds[idx];
  g_c[idx] = ds[65536 + idx];
  if (idx < BB*EMBD) g_prev[idx] = 0.f;
}

// ---------------- gates: [prev|h] @ [W_ih|W_hh]^T, split-K 4 ----------------
__global__ void __launch_bounds__(256) k_gates(const float* __restrict__ Wih,
                                               const float* __restrict__ Whh){
  int tid = threadIdx.x, tx = tid & 31, ty = tid >> 5;
  int n0 = blockIdx.x*128, part = blockIdx.y;
  ull accv[4][4] = {};
  ALd  a{g_prev, g_h, 512, 1024, 512, tid, {}};
  BLdT b{Wih + (size_t)n0*512, Whh + (size_t)n0*1024, 512, 1024, 512, tid, {}, {}};
  gemm_run(a, b, part*384, 24, accv, tx, ty);
  float c[8][4]; unpack_acc(accv, c);
  float* o = g_gpart + (size_t)part*BB*G4;
#pragma unroll
  for (int i = 0; i < 8; ++i)
    *reinterpret_cast<float4*>(o + (size_t)(8*ty+i)*G4 + n0 + 4*tx) =
      make_float4(c[i][0], c[i][1], c[i][2], c[i][3]);
}

// ---------------- LSTM elementwise (sums 4 split-K parts + bias); resets amax ----------------
__global__ void k_lstm(const float* __restrict__ bl){
  int idx = blockIdx.x*blockDim.x + threadIdx.x;   // 65536
  int m = idx >> 10, j = idx & 1023;
  float gi = bl[j], gf = bl[1024+j], gg = bl[2048+j], go = bl[3072+j];
#pragma unroll
  for (int p = 0; p < 4; ++p){
    const float* gp = g_gpart + (size_t)p*BB*G4 + (size_t)m*G4 + j;
    gi += gp[0]; gf += gp[1024]; gg += gp[2048]; go += gp[3072];
  }
  float c = g_c[idx];
  float cn = sigmoidf_(gf)*c + sigmoidf_(gi)*tanhf(gg);
  g_c[idx] = cn;
  g_h[idx] = sigmoidf_(go)*tanhf(cn);
  if (blockIdx.x == 0 && threadIdx.x < BB) g_amax[threadIdx.x] = 0ull;
}

// ---------------- q = h @ W_attproj, split-K 8 ----------------
__global__ void __launch_bounds__(256) k_q(const float* __restrict__ Wap){
  int tid = threadIdx.x, tx = tid & 31, ty = tid >> 5;
  int n0 = blockIdx.x*128, part = blockIdx.y;
  ull accv[4][4] = {};
  ALd  a{g_h, g_h, 1024, 1024, 1<<30, tid, {}};
  BLdD b{Wap + n0, 1024, tid, {}, {}};
  gemm_run(a, b, part*128, 8, accv, tx, ty);
  float c[8][4]; unpack_acc(accv, c);
  float* o = g_qpart + (size_t)part*BB*EE;
#pragma unroll
  for (int i = 0; i < 8; ++i)
    *reinterpret_cast<float4*>(o + (size_t)(8*ty+i)*EE + n0 + 4*tx) =
      make_float4(c[i][0], c[i][1], c[i][2], c[i][3]);
}

// ---------------- fused attention: scores -> masked softmax -> context (512 thr) ----------------
__global__ void k_attn(const float* __restrict__ enc, const int* __restrict__ enc_len){
  __shared__ float qv[1024];
  __shared__ float sc[128];
  __shared__ float sr[128];
  int tid = threadIdx.x, b = blockIdx.x;
  for (int e = tid; e < 1024; e += 512){
    float s = 0.f;
#pragma unroll
    for (int p = 0; p < 8; ++p) s += g_qpart[(size_t)p*BB*EE + (size_t)b*EE + e];
    qv[e] = s;
  }
  __syncthreads();
  const float* eb = enc + (size_t)b*SS*EE;
  int w = tid >> 5, lane = tid & 31;
  for (int s = w; s < 128; s += 16){
    const float* er = eb + (size_t)s*EE;
    float acc = 0.f;
    for (int e = lane; e < 1024; e += 32) acc = fmaf(er[e], qv[e], acc);
#pragma unroll
    for (int o = 16; o; o >>= 1) acc += __shfl_xor_sync(0xffffffffu, acc, o);
    if (lane == 0) sc[s] = acc;
  }
  __syncthreads();
  int len = enc_len[b];
  bool act = tid < 128;
  float v = -1e9f;
  if (act){ v = (tid < len) ? sc[tid] : -1e9f; sr[tid] = v; }
  __syncthreads();
  for (int o = 64; o; o >>= 1){ if (tid < o) sr[tid] = fmaxf(sr[tid], sr[tid+o]); __syncthreads(); }
  float mx = sr[0]; __syncthreads();
  float ev = 0.f;
  if (act){ ev = expf(v - mx); sr[tid] = ev; }
  __syncthreads();
  for (int o = 64; o; o >>= 1){ if (tid < o) sr[tid] += sr[tid+o]; __syncthreads(); }
  float inv = 1.f / sr[0];
  __syncthreads();
  if (act) sc[tid] = ev * inv;
  __syncthreads();
  float a0 = 0.f, a1 = 0.f;
  for (int s = 0; s < 128; ++s){
    float al = sc[s];
    const float* er = eb + (size_t)s*EE;
    a0 = fmaf(al, er[tid      ], a0);
    a1 = fmaf(al, er[tid + 512], a1);
  }
  float* ct = g_ct + (size_t)b*EE;
  ct[tid] = a0; ct[tid+512] = a1;
}

// ---------------- dec = [h | c_t] @ W_out^T, split-K 8 ----------------
__global__ void __launch_bounds__(256) k_dec(const float* __restrict__ Wout){
  int tid = threadIdx.x, tx = tid & 31, ty = tid >> 5;
  int n0 = blockIdx.x*128, part = blockIdx.y;
  ull accv[4][4] = {};
  ALd  a{g_h, g_ct, 1024, 1024, 1024, tid, {}};
  BLdT b{Wout + (size_t)n0*2048, Wout + (size_t)n0*2048, 2048, 2048, 1<<30, tid, {}, {}};
  gemm_run(a, b, part*256, 16, accv, tx, ty);
  float c[8][4]; unpack_acc(accv, c);
  float* o = g_dpart + (size_t)part*BB*EMBD;
#pragma unroll
  for (int i = 0; i < 8; ++i)
    *reinterpret_cast<float4*>(o + (size_t)(8*ty+i)*EMBD + n0 + 4*tx) =
      make_float4(c[i][0], c[i][1], c[i][2], c[i][3]);
}

// ---------------- sum dec split-K parts ----------------
__global__ void k_dsum(){
  int i = blockIdx.x*blockDim.x + threadIdx.x;   // 8192 float4
  float4 s = make_float4(0.f,0.f,0.f,0.f);
#pragma unroll
  for (int p = 0; p < 8; ++p){
    float4 w = reinterpret_cast<const float4*>(g_dpart)[p*8192 + i];
    s.x += w.x; s.y += w.y; s.z += w.z; s.w += w.w;
  }
  reinterpret_cast<float4*>(g_dec)[i] = s;
}

// ---------------- logits = dec @ W_vocab^T -> d_out, + argmax ----------------
__global__ void __launch_bounds__(256) k_vocab(const float* __restrict__ Wv,
                                               float* __restrict__ out, int t){
  int tid = threadIdx.x, tx = tid & 31, ty = tid >> 5;
  int n0 = blockIdx.x*128;
  ull accv[4][4] = {};
  ALd  a{g_dec, g_dec, 512, 512, 1<<30, tid, {}};
  BLdT b{Wv + (size_t)n0*512, Wv + (size_t)n0*512, 512, 512, 1<<30, tid, {}, {}};
  gemm_run(a, b, 0, 32, accv, tx, ty);
  float c[8][4]; unpack_acc(accv, c);
#pragma unroll
  for (int i = 0; i < 8; ++i){
    int m = 8*ty + i;
    float bv = c[i][0]; int bn = n0 + 4*tx;
#pragma unroll
    for (int j = 1; j < 4; ++j)
      if (c[i][j] > bv){ bv = c[i][j]; bn = n0 + 4*tx + j; }
    ull pk = packmax(bv, bn);
#pragma unroll
    for (int o = 16; o; o >>= 1){
      ull other = __shfl_xor_sync(0xffffffffu, pk, o);
      if (other > pk) pk = other;
    }
    if (tx == 0) atomicMax(&g_amax[m], pk);
    __stcs(reinterpret_cast<float4*>(out + ((size_t)m*TT + t)*VV + n0 + 4*tx),
           make_float4(c[i][0], c[i][1], c[i][2], c[i][3]));
  }
}

// ---------------- greedy symbol -> prev embedding ----------------
__global__ void k_update(const float* __restrict__ emb){
  int b = blockIdx.x;
  unsigned int low = (unsigned int)(g_amax[b] & 0xFFFFFFFFull);
  int sym = 0x7FFFFFFF - (int)low;
  g_prev[(size_t)b*EMBD + threadIdx.x] = emb[(size_t)sym*EMBD + threadIdx.x];
}

// ---------------- in-place log-softmax over V ----------------
__global__ void k_lsm(float* __restrict__ out){
  __shared__ float sr[256];
  float* p = out + (size_t)blockIdx.x * VV;
  int tid = threadIdx.x;
  float mx = -3.4e38f;
  for (int i = tid; i < VV; i += 256) mx = fmaxf(mx, __ldcs(p+i));
  sr[tid] = mx; __syncthreads();
  for (int o = 128; o; o >>= 1){ if (tid < o) sr[tid] = fmaxf(sr[tid], sr[tid+o]); __syncthreads(); }
  mx = sr[0]; __syncthreads();
  float s = 0.f;
  for (int i = tid; i < VV; i += 256) s += expf(__ldcs(p+i) - mx);
  sr[tid] = s; __syncthreads();
  for (int o = 128; o; o >>= 1){ if (tid < o) sr[tid] += sr[tid+o]; __syncthreads(); }
  float shift = mx + logf(sr[0]);
  __syncthreads();
  for (int i = tid; i < VV; i += 256) __stcs(p+i, __ldcs(p+i) - shift);
}

// tl is provably always T=50
__global__ void k_tail(float* __restrict__ out){ out[NPRED + threadIdx.x] = 50.0f; }

extern "C" void kernel_launch(void* const* d_in, const int* in_sizes, int n_in,
                              void* d_out, int out_size){
  const float* ds   = (const float*)d_in[0];
  const float* enc  = (const float*)d_in[1];
  const int*   elen = (const int*)  d_in[2];
  // d_in[3] = tgt (unused in eval mode)
  const float* Wih  = (const float*)d_in[4];
  const float* Whh  = (const float*)d_in[5];
  const float* bl   = (const float*)d_in[6];
  const float* Wap  = (const float*)d_in[7];
  const float* Wout = (const float*)d_in[8];
  const float* Wv   = (const float*)d_in[9];
  const float* emb  = (const float*)d_in[10];
  float* out = (float*)d_out;

  k_init<<<256,256>>>(ds);
  for (int t = 0; t < TT; ++t){
    k_gates<<<dim3(32,4),256>>>(Wih, Whh);
    k_lstm<<<256,256>>>(bl);
    k_q<<<dim3(8,8),256>>>(Wap);
    k_attn<<<64,512>>>(enc, elen);
    k_dec<<<dim3(4,8),256>>>(Wout);
    k_dsum<<<32,256>>>();
    k_vocab<<<250,256>>>(Wv, out, t);
    k_update<<<64,512>>>(emb);
  }
  k_lsm<<<3200,256>>>(out);
  if (out_size >= NPRED + 64) k_tail<<<1,64>>>(out);
}